// round 3
// baseline (speedup 1.0000x reference)
#include <cuda_runtime.h>
#include <cstdint>

// ---------------------------------------------------------------------------
// PointCloudGenerator: neural-SDF sphere tracing, fully fused.
// R3: 128-thread CTAs, 16x8 register tiles (acc = 64 u64), native f32x2 A
// fragments, software-pipelined smem loads, 2 CTAs/SM, one co-resident wave.
// ---------------------------------------------------------------------------

// smem: Wb 16384 f (2x 64x128 W2 chunk buffers; 'red' aliases this),
//       H1Tc 8192 f, tables 1536 f, ray state 1024 f  => 108544 B
#define SMEM_FLOATS (16384 + 8192 + 1536 + 1024)
#define SMEM_BYTES  (SMEM_FLOATS * 4)

__device__ float g_c1[256];

__device__ __forceinline__ uint64_t pk2(float lo, float hi) {
    uint64_t r;
    asm("mov.b64 %0, {%1,%2};" : "=l"(r) : "f"(lo), "f"(hi));
    return r;
}
__device__ __forceinline__ void upk2(uint64_t v, float& lo, float& hi) {
    asm("mov.b64 {%0,%1}, %2;" : "=f"(lo), "=f"(hi) : "l"(v));
}
__device__ __forceinline__ void ffma2(uint64_t& d, uint64_t a, uint64_t b) {
    asm("fma.rn.f32x2 %0, %1, %2, %0;" : "+l"(d) : "l"(a), "l"(b));
}
__device__ __forceinline__ void cpa16(float* dst, const float* src) {
    uint32_t s = (uint32_t)__cvta_generic_to_shared(dst);
    asm volatile("cp.async.cg.shared.global [%0], [%1], 16;" :: "r"(s), "l"(src));
}

// c1[j] = b1[j] + sum_k lat[k] * W1[3+k][j]  -- one block per j, double accum
__global__ void c1_kernel(const float* __restrict__ lg, const float* __restrict__ le,
                          const float* __restrict__ la, const float* __restrict__ W1,
                          const float* __restrict__ b1) {
    int j = blockIdx.x;
    int t = threadIdx.x;
    double acc = 0.0;
    for (int k = t; k < 484; k += 128) {
        float lv = (k < 256) ? lg[k] : (k < 356 ? le[k - 256] : la[k - 356]);
        acc += (double)lv * (double)W1[(size_t)(3 + k) * 256 + j];
    }
    #pragma unroll
    for (int o = 16; o > 0; o >>= 1)
        acc += __shfl_down_sync(0xffffffffu, acc, o);
    __shared__ double part[4];
    if ((t & 31) == 0) part[t >> 5] = acc;
    __syncthreads();
    if (t == 0)
        g_c1[j] = (float)(part[0] + part[1] + part[2] + part[3] + (double)b1[j]);
}

__global__ void __launch_bounds__(128, 2)
trace_kernel(const float* __restrict__ W1, const float* __restrict__ W2,
             const float* __restrict__ b2g, const float* __restrict__ W3,
             const float* __restrict__ b3, float* __restrict__ out) {
    extern __shared__ float smf[];
    float* Wb   = smf;                 // 2 x [64 k][128 n] = 16384 f
    float* red  = smf;                 // [16][132] aliases Wb (used post-GEMM)
    float* H1Tc = smf + 16384;         // [64 k][128 rays]  = 8192 f
    float* w10  = smf + 24576;
    float* w11  = w10 + 256;
    float* w12  = w11 + 256;
    float* c1s  = w12 + 256;
    float* b2s  = c1s + 256;
    float* w3s  = b2s + 256;
    float* px   = smf + 26112;
    float* py   = px + 128;
    float* pz   = py + 128;
    float* tt   = pz + 128;
    float* ddx  = tt + 128;
    float* ddy  = ddx + 128;
    float* ddz  = ddy + 128;
    int*   act  = (int*)(ddz + 128);

    const int t  = threadIdx.x;     // 128 threads
    const int tx = t & 15;          // col group (8 cols)
    const int ty = t >> 4;          // ray group (16 rays)

    // static tables (256 entries, 128 threads)
    #pragma unroll
    for (int i = 0; i < 2; ++i) {
        int j = t + i * 128;
        w10[j] = W1[j];
        w11[j] = W1[256 + j];
        w12[j] = W1[512 + j];
        c1s[j] = g_c1[j];
        b2s[j] = b2g[j];
        w3s[j] = W3[j * 4];   // only column 0 of W3 is live
    }

    // ray setup (mirrors _rays in fp32)
    {
        int g    = blockIdx.x * 128 + t;
        int view = g >> 14;
        int pix  = g & 16383;
        int iu = pix >> 7, jv = pix & 127;
        float u = (iu + 0.5f) / 128.0f - 0.5f;
        float v = 0.5f - (jv + 0.5f) / 128.0f;
        float nrm = sqrtf(__fadd_rn(__fadd_rn(__fmul_rn(u, u), __fmul_rn(v, v)), 1.0f));
        float d0x = u / nrm, d0y = v / nrm, d0z = -1.0f / nrm;
        float c = 0.86602540378443865f;          // cos(30 deg)
        float s = view ? 0.5f : -0.5f;           // sin(rho), rho = -30, +30
        float dirx = __fadd_rn(__fmul_rn(c, d0x), __fmul_rn(s, d0z));
        float diry = d0y;
        float dirz = __fadd_rn(__fmul_rn(-s, d0x), __fmul_rn(c, d0z));
        ddx[t] = dirx; ddy[t] = diry; ddz[t] = dirz;
        px[t] = __fadd_rn(__fmul_rn(s, 2.2f), __fmul_rn(2.2f, dirx));
        py[t] = __fmul_rn(2.2f, diry);
        pz[t] = __fadd_rn(__fmul_rn(c, 2.2f), __fmul_rn(2.2f, dirz));
        tt[t] = 0.0f;
        act[t] = 1;
    }
    __syncthreads();

    float dcur = 0.0f;

    for (int e = 0; e < 7; ++e) {
        float sp[16];
        #pragma unroll
        for (int q = 0; q < 16; ++q) sp[q] = 0.0f;

        #pragma unroll 1
        for (int nh = 0; nh < 2; ++nh) {
            uint64_t acc[8][8];     // 8 ray-pairs x 8 cols
            #pragma unroll
            for (int p = 0; p < 8; ++p)
                #pragma unroll
                for (int n = 0; n < 8; ++n) acc[p][n] = 0ull;

            const float* wsrc = W2 + nh * 128;
            const int r0 = t >> 5;          // 0..3
            const int c0 = (t & 31) * 4;    // 0..124

            auto issue = [&](int kc, int b) {
                float*       dst = Wb + b * 8192 + r0 * 128 + c0;
                const float* src = wsrc + (size_t)(kc * 64 + r0) * 256 + c0;
                #pragma unroll
                for (int i = 0; i < 16; ++i)
                    cpa16(dst + i * 512, src + i * 1024);
                asm volatile("cp.async.commit_group;" ::: "memory");
            };
            issue(0, 0);
            issue(1, 1);

            #pragma unroll 1
            for (int kc = 0; kc < 4; ++kc) {
                // ---- layer-1 chunk: thread t computes ray t, j = kc*64+jj ----
                {
                    float x = px[t], yv = py[t], zv = pz[t];
                    const int jb = kc * 64;
                    #pragma unroll 8
                    for (int jj = 0; jj < 64; ++jj) {
                        int j = jb + jj;
                        float h = fmaf(x, w10[j],
                                  fmaf(yv, w11[j],
                                  fmaf(zv, w12[j], c1s[j])));
                        H1Tc[jj * 128 + t] = fmaxf(h, 0.0f);
                    }
                }
                if (kc == 3) asm volatile("cp.async.wait_group 0;" ::: "memory");
                else         asm volatile("cp.async.wait_group 1;" ::: "memory");
                __syncthreads();

                const float* Bp = Wb + (kc & 1) * 8192 + tx * 8;
                const float* Ap = H1Tc + ty * 16;

                // software pipeline: prefetch kk+1 while doing kk's FMAs
                ulonglong2 cA0 = *(const ulonglong2*)(Ap);
                ulonglong2 cA1 = *(const ulonglong2*)(Ap + 4);
                ulonglong2 cA2 = *(const ulonglong2*)(Ap + 8);
                ulonglong2 cA3 = *(const ulonglong2*)(Ap + 12);
                float4 cB0 = *(const float4*)(Bp);
                float4 cB1 = *(const float4*)(Bp + 4);

                #pragma unroll 1
                for (int kk = 0; kk < 64; ++kk) {
                    const int kn = (kk + 1) & 63;       // wraps; value unused at kk=63
                    ulonglong2 nA0 = *(const ulonglong2*)(Ap + kn * 128);
                    ulonglong2 nA1 = *(const ulonglong2*)(Ap + kn * 128 + 4);
                    ulonglong2 nA2 = *(const ulonglong2*)(Ap + kn * 128 + 8);
                    ulonglong2 nA3 = *(const ulonglong2*)(Ap + kn * 128 + 12);
                    float4 nB0 = *(const float4*)(Bp + kn * 128);
                    float4 nB1 = *(const float4*)(Bp + kn * 128 + 4);

                    uint64_t ap[8] = { cA0.x, cA0.y, cA1.x, cA1.y,
                                       cA2.x, cA2.y, cA3.x, cA3.y };
                    uint64_t bd[8] = { pk2(cB0.x, cB0.x), pk2(cB0.y, cB0.y),
                                       pk2(cB0.z, cB0.z), pk2(cB0.w, cB0.w),
                                       pk2(cB1.x, cB1.x), pk2(cB1.y, cB1.y),
                                       pk2(cB1.z, cB1.z), pk2(cB1.w, cB1.w) };
                    #pragma unroll
                    for (int p = 0; p < 8; ++p)
                        #pragma unroll
                        for (int n = 0; n < 8; ++n)
                            ffma2(acc[p][n], ap[p], bd[n]);

                    cA0 = nA0; cA1 = nA1; cA2 = nA2; cA3 = nA3;
                    cB0 = nB0; cB1 = nB1;
                }
                __syncthreads();
                if (kc < 2) issue(kc + 2, kc & 1);
            }

            // epilogue: bias + relu + partial dot with W3[:,0]
            #pragma unroll
            for (int p = 0; p < 8; ++p) {
                #pragma unroll
                for (int n = 0; n < 8; ++n) {
                    float lo, hi;
                    upk2(acc[p][n], lo, hi);
                    int col = nh * 128 + tx * 8 + n;
                    lo = fmaxf(__fadd_rn(lo, b2s[col]), 0.0f);
                    hi = fmaxf(__fadd_rn(hi, b2s[col]), 0.0f);
                    float w3v = w3s[col];
                    sp[2 * p]     = fmaf(lo, w3v, sp[2 * p]);
                    sp[2 * p + 1] = fmaf(hi, w3v, sp[2 * p + 1]);
                }
            }
        }

        // red aliases Wb: all GEMM reads of Wb completed (sync after kc=3)
        #pragma unroll
        for (int q = 0; q < 16; ++q) red[tx * 132 + ty * 16 + q] = sp[q];
        __syncthreads();

        // ---- sdf + ray update (one thread per ray) ----
        int pred = 0;
        {
            float ssum = 0.0f;
            #pragma unroll
            for (int k2 = 0; k2 < 16; ++k2) ssum = __fadd_rn(ssum, red[k2 * 132 + t]);
            float res = __fadd_rn(ssum, b3[0]);
            float x = px[t], yv = py[t], zv = pz[t];
            float nrm = sqrtf(__fadd_rn(__fadd_rn(__fmul_rn(x, x), __fmul_rn(yv, yv)),
                                        __fmul_rn(zv, zv)));
            float d = __fadd_rn(__fsub_rn(nrm, 0.7f), res);
            dcur = d;
            if (e < 6) {
                int a   = act[t];
                int hit = fabsf(d) < 1e-3f;
                float adv = (a && !hit) ? __fmul_rn(1.41421356237309515f, d) : 0.0f;
                px[t] = __fadd_rn(x,  __fmul_rn(adv, ddx[t]));
                py[t] = __fadd_rn(yv, __fmul_rn(adv, ddy[t]));
                pz[t] = __fadd_rn(zv, __fmul_rn(adv, ddz[t]));
                float tn = __fadd_rn(tt[t], adv);
                tt[t] = tn;
                act[t] = (a && !hit && (tn < 3.5f)) ? 1 : 0;
                pred = (adv != 0.0f);
            }
        }
        int anyAdv = __syncthreads_or(pred);
        // if no ray moved, every remaining eval is bit-identical to dcur
        if (e < 6 && !anyAdv) break;
    }

    {
        int g = blockIdx.x * 128 + t;
        bool m = fabsf(dcur) < 1e-3f;
        out[3 * g + 0] = m ? px[t] : 0.0f;
        out[3 * g + 1] = m ? py[t] : 0.0f;
        out[3 * g + 2] = m ? pz[t] : 0.0f;
    }
}

extern "C" void kernel_launch(void* const* d_in, const int* in_sizes, int n_in,
                              void* d_out, int out_size) {
    const float* lg = (const float*)d_in[0];
    const float* le = (const float*)d_in[1];
    const float* la = (const float*)d_in[2];
    const float* W1 = (const float*)d_in[3];
    const float* b1 = (const float*)d_in[4];
    const float* W2 = (const float*)d_in[5];
    const float* b2 = (const float*)d_in[6];
    const float* W3 = (const float*)d_in[7];
    const float* b3 = (const float*)d_in[8];
    float* out = (float*)d_out;

    cudaFuncSetAttribute(trace_kernel, cudaFuncAttributeMaxDynamicSharedMemorySize,
                         SMEM_BYTES);
    c1_kernel<<<256, 128>>>(lg, le, la, W1, b1);
    trace_kernel<<<256, 128, SMEM_BYTES>>>(W1, W2, b2, W3, b3, out);
}